// round 2
// baseline (speedup 1.0000x reference)
#include <cuda_runtime.h>

#define B_    16
#define N_    2048
#define D_    1024
#define KH    15
#define KL    5
#define ROWS  320      // B_*KH + B_*KL
#define HROWS 240      // B_*KH
#define SPLITK 8
#define KC    (D_ / SPLITK)   // 128

// ---------------- scratch (no allocations allowed) ----------------
__device__ unsigned int g_pmax[B_];
__device__ unsigned int g_pmin[B_];
__device__ float        g_psum[B_];
__device__ int          g_idx[ROWS];
__device__ int          g_val[ROWS];
__device__ int          g_lab[ROWS];
__device__ __align__(16) float g_Gk[SPLITK][ROWS * ROWS];
__device__ float        g_c[B_];

// ---------------- helpers ----------------
__device__ __forceinline__ unsigned long long u64min(unsigned long long a,
                                                     unsigned long long b) {
    return a < b ? a : b;
}

__device__ __forceinline__ unsigned long long f32x2_fma(unsigned long long c,
                                                        unsigned long long a,
                                                        unsigned long long b) {
    asm("fma.rn.f32x2 %0, %1, %2, %0;" : "+l"(c) : "l"(a), "l"(b));
    return c;
}

__device__ __forceinline__ unsigned long long dup_f32(float x) {
    unsigned long long r;
    unsigned u = __float_as_uint(x);
    asm("mov.b64 %0, {%1, %1};" : "=l"(r) : "r"(u));
    return r;
}

// ---------------- 1: per-bag min/max/sum partials (16 blocks) ----------------
__global__ void k_reduce(const float* __restrict__ score) {
    __shared__ unsigned int smx[8], smn[8];
    __shared__ float ssum[8];
    int b = blockIdx.x, tid = threadIdx.x;
    unsigned int mx = 0u, mn = 0xFFFFFFFFu;
    float s = 0.f;
#pragma unroll
    for (int i = 0; i < 8; i++) {
        float v = score[b * N_ + tid + i * 256];
        unsigned int bb = __float_as_uint(v);   // score >= 0 -> bits monotonic
        mx = max(mx, bb);
        mn = min(mn, bb);
        s += v;
    }
#pragma unroll
    for (int o = 16; o; o >>= 1) {
        mx = max(mx, __shfl_down_sync(0xffffffffu, mx, o));
        mn = min(mn, __shfl_down_sync(0xffffffffu, mn, o));
        s += __shfl_down_sync(0xffffffffu, s, o);
    }
    if ((tid & 31) == 0) { smx[tid >> 5] = mx; smn[tid >> 5] = mn; ssum[tid >> 5] = s; }
    __syncthreads();
    if (tid == 0) {
        for (int w = 1; w < 8; w++) {
            mx = max(mx, smx[w]); mn = min(mn, smn[w]); s += ssum[w];
        }
        g_pmax[b] = mx; g_pmin[b] = mn; g_psum[b] = s;
    }
}

// ---------------- 2: per-bag selection (16 blocks, shuffle extraction) -------
// key = (float_bits(score) << 32) | index  -> lexicographic (score, idx),
// matching jnp stable ascending argsort semantics (score >= 0).
__global__ void k_select(const float* __restrict__ score,
                         const int* __restrict__ label) {
    __shared__ unsigned long long s_w[2][8];
    __shared__ float s_gmax, s_gmin;
    int b = blockIdx.x, tid = threadIdx.x;

    if (tid == 0) {
        unsigned mx = 0u, mn = 0xFFFFFFFFu;
        for (int i = 0; i < B_; i++) { mx = max(mx, g_pmax[i]); mn = min(mn, g_pmin[i]); }
        s_gmax = __uint_as_float(mx);
        s_gmin = __uint_as_float(mn);
    }

    float sc[8];
#pragma unroll
    for (int i = 0; i < 8; i++) sc[i] = score[b * N_ + tid + i * 256];
    __syncthreads();
    float gmax = s_gmax, gmin = s_gmin;

    unsigned long long key[8];
    int parity = 0;

    // ---- HIGH: 15 smallest keys with score in [gmax-0.3, gmax] ----
    {
        float lo = gmax - 0.3f, hi = gmax;
#pragma unroll
        for (int i = 0; i < 8; i++) {
            key[i] = (sc[i] >= lo && sc[i] <= hi)
                ? (((unsigned long long)__float_as_uint(sc[i]) << 32) | (unsigned)(tid + i * 256))
                : ~0ULL;
        }
        for (int t = 0; t < KH; t++) {
            unsigned long long m = key[0];
#pragma unroll
            for (int i = 1; i < 8; i++) m = u64min(m, key[i]);
#pragma unroll
            for (int o = 16; o; o >>= 1) m = u64min(m, __shfl_down_sync(0xffffffffu, m, o));
            if ((tid & 31) == 0) s_w[parity][tid >> 5] = m;
            __syncthreads();
            if (tid < 32) {
                unsigned long long v = (tid < 8) ? s_w[parity][tid] : ~0ULL;
#pragma unroll
                for (int o = 4; o; o >>= 1) v = u64min(v, __shfl_down_sync(0xffffffffu, v, o));
                if (tid == 0) s_w[parity][0] = v;
            }
            __syncthreads();
            unsigned long long best = s_w[parity][0];
            parity ^= 1;
#pragma unroll
            for (int i = 0; i < 8; i++) if (key[i] == best) key[i] = ~0ULL;
            if (tid == 0) {
                int r = b * KH + t;
                if (best != ~0ULL) {
                    g_val[r] = 1;
                    g_idx[r] = b * N_ + (int)(best & 0xFFFFFFFFULL);
                } else {
                    g_val[r] = 0;
                    g_idx[r] = 0;
                }
                g_lab[r] = label[b];
            }
        }
    }

    // ---- LOW: up to 10 smallest keys in [gmin, gmin+1e-9]; keep even ranks --
    {
        float lo = gmin, hi = gmin + 1e-9f;
#pragma unroll
        for (int i = 0; i < 8; i++) {
            key[i] = (sc[i] >= lo && sc[i] <= hi)
                ? (((unsigned long long)__float_as_uint(sc[i]) << 32) | (unsigned)(tid + i * 256))
                : ~0ULL;
        }
        unsigned long long sel[10];
        for (int t = 0; t < 10; t++) {
            unsigned long long m = key[0];
#pragma unroll
            for (int i = 1; i < 8; i++) m = u64min(m, key[i]);
#pragma unroll
            for (int o = 16; o; o >>= 1) m = u64min(m, __shfl_down_sync(0xffffffffu, m, o));
            if ((tid & 31) == 0) s_w[parity][tid >> 5] = m;
            __syncthreads();
            if (tid < 32) {
                unsigned long long v = (tid < 8) ? s_w[parity][tid] : ~0ULL;
#pragma unroll
                for (int o = 4; o; o >>= 1) v = u64min(v, __shfl_down_sync(0xffffffffu, v, o));
                if (tid == 0) s_w[parity][0] = v;
            }
            __syncthreads();
            unsigned long long best = s_w[parity][0];
            parity ^= 1;
#pragma unroll
            for (int i = 0; i < 8; i++) if (key[i] == best) key[i] = ~0ULL;
            sel[t] = best;
        }
        if (tid == 0) {
            for (int j = 0; j < KL; j++) {
                unsigned long long k = sel[2 * j];
                int r = HROWS + b * KL + j;
                if (k != ~0ULL) {
                    g_val[r] = 1;
                    g_idx[r] = b * N_ + (int)(k & 0xFFFFFFFFULL);
                } else {
                    g_val[r] = 0;
                    g_idx[r] = 0;
                }
                g_lab[r] = 2;  // N_CLASSES
            }
        }
    }
}

// ---- 3: gram G = X X^T (320x320, K=1024) with fused gather, f32x2 FMA ------
#define BM 64
#define BN 64
#define BK 16
__global__ void __launch_bounds__(256) k_gemm(const float* __restrict__ fea) {
    __shared__ __align__(16) float As[BK][BM + 2];
    __shared__ __align__(16) float Bs[BK][BN + 2];
    int bm = blockIdx.x, bn = blockIdx.y, kz = blockIdx.z;
    int tid = threadIdx.x;
    int tx = tid & 15, ty = tid >> 4;
    int tx4 = tx * 4, ty4 = ty * 4;

    unsigned long long cc[4][2];
#pragma unroll
    for (int i = 0; i < 4; i++) { cc[i][0] = 0ULL; cc[i][1] = 0ULL; }

    int loadRow = tid >> 2;           // 0..63
    int loadK4  = (tid & 3) * 4;      // 0,4,8,12
    // indirect gather: invalid rows point at row 0; masked in k_rowloss
    const float* A0 = fea + (size_t)g_idx[bm * BM + loadRow] * D_ + kz * KC;
    const float* B0 = fea + (size_t)g_idx[bn * BN + loadRow] * D_ + kz * KC;

    for (int k0 = 0; k0 < KC; k0 += BK) {
        float4 a  = *(const float4*)(A0 + k0 + loadK4);
        float4 b4 = *(const float4*)(B0 + k0 + loadK4);
        As[loadK4 + 0][loadRow] = a.x;
        As[loadK4 + 1][loadRow] = a.y;
        As[loadK4 + 2][loadRow] = a.z;
        As[loadK4 + 3][loadRow] = a.w;
        Bs[loadK4 + 0][loadRow] = b4.x;
        Bs[loadK4 + 1][loadRow] = b4.y;
        Bs[loadK4 + 2][loadRow] = b4.z;
        Bs[loadK4 + 3][loadRow] = b4.w;
        __syncthreads();
#pragma unroll
        for (int k = 0; k < BK; k++) {
            float2 a01 = *(const float2*)&As[k][ty4];
            float2 a23 = *(const float2*)&As[k][ty4 + 2];
            unsigned long long bp0 = *(const unsigned long long*)&Bs[k][tx4];
            unsigned long long bp1 = *(const unsigned long long*)&Bs[k][tx4 + 2];
            unsigned long long A0d = dup_f32(a01.x);
            unsigned long long A1d = dup_f32(a01.y);
            unsigned long long A2d = dup_f32(a23.x);
            unsigned long long A3d = dup_f32(a23.y);
            cc[0][0] = f32x2_fma(cc[0][0], A0d, bp0);
            cc[0][1] = f32x2_fma(cc[0][1], A0d, bp1);
            cc[1][0] = f32x2_fma(cc[1][0], A1d, bp0);
            cc[1][1] = f32x2_fma(cc[1][1], A1d, bp1);
            cc[2][0] = f32x2_fma(cc[2][0], A2d, bp0);
            cc[2][1] = f32x2_fma(cc[2][1], A2d, bp1);
            cc[3][0] = f32x2_fma(cc[3][0], A3d, bp0);
            cc[3][1] = f32x2_fma(cc[3][1], A3d, bp1);
        }
        __syncthreads();
    }

    float* out = g_Gk[kz];
#pragma unroll
    for (int i = 0; i < 4; i++) {
        unsigned lo0, hi0, lo1, hi1;
        asm("mov.b64 {%0, %1}, %2;" : "=r"(lo0), "=r"(hi0) : "l"(cc[i][0]));
        asm("mov.b64 {%0, %1}, %2;" : "=r"(lo1), "=r"(hi1) : "l"(cc[i][1]));
        float4 v = make_float4(__uint_as_float(lo0), __uint_as_float(hi0),
                               __uint_as_float(lo1), __uint_as_float(hi1));
        int row = bm * BM + ty4 + i;
        *(float4*)(out + (size_t)row * ROWS + bn * BN + tx4) = v;
    }
}

// ---------------- 4: per-bag contrastive (16 blocks) ----------------
__global__ void k_rowloss() {
    __shared__ int s_val[ROWS];
    __shared__ int s_lab[ROWS];
    __shared__ float red[16];
    int b = blockIdx.x, tid = threadIdx.x;
    for (int i = tid; i < ROWS; i += 256) { s_val[i] = g_val[i]; s_lab[i] = g_lab[i]; }
    __syncthreads();

    float bagsum = 0.f;
    int bagcnt = 0;
    for (int qi = 0; qi < KH + KL; qi++) {
        int q = (qi < KH) ? b * KH + qi : HROWS + b * KL + (qi - KH);
        int labq = s_lab[q];
        float den = 0.f, num = 0.f;
        for (int n = tid; n < ROWS; n += 256) {
            float g = 0.f;
#pragma unroll
            for (int s = 0; s < SPLITK; s++) g += g_Gk[s][q * ROWS + n];
            float e = expf(g * 0.0625f);     // TAU = 16
            e = s_val[n] ? e : 0.f;
            den += e;
            if (s_lab[n] == labq) num += e;
        }
#pragma unroll
        for (int o = 16; o; o >>= 1) {
            den += __shfl_down_sync(0xffffffffu, den, o);
            num += __shfl_down_sync(0xffffffffu, num, o);
        }
        if ((tid & 31) == 0) { red[tid >> 5] = den; red[8 + (tid >> 5)] = num; }
        __syncthreads();
        if (tid == 0) {
            float d = 0.f, nm = 0.f;
            for (int w = 0; w < 8; w++) { d += red[w]; nm += red[8 + w]; }
            if (s_val[q]) bagsum += -logf(nm / d);
            bagcnt += s_val[q];
        }
        __syncthreads();
    }
    if (tid == 0) g_c[b] = bagsum / (float)bagcnt;
}

// ---------------- 5: final scalar ----------------
__global__ void k_final(const float* __restrict__ t_logit,
                        const float* __restrict__ ori,
                        const float* __restrict__ l2w,
                        float* __restrict__ out) {
    if (threadIdx.x == 0) {
        float contr = 0.f;
        for (int b = 0; b < B_; b++) contr += g_c[b];
        contr /= (float)B_;

        float t = t_logit[0];
        float ce = 0.f;
        for (int b = 0; b < B_; b++) {
            float se = expf(ori[b * 2 + 0]) + expf(ori[b * 2 + 1]);
            ce += -logf(expf(t) / se);
        }
        ce /= (float)B_;

        unsigned mx = 0u;
        float sum = 0.f;
        for (int i = 0; i < B_; i++) { mx = max(mx, g_pmax[i]); sum += g_psum[i]; }
        float gmax = __uint_as_float(mx);
        float meanv = sum / (float)(B_ * N_);
        float Dm = meanv / gmax;
        float l2 = 0.0001f * (1.f - Dm) * (1.f - Dm) * l2w[0];

        out[0] = contr + ce + l2;
    }
}

// ---------------- launch ----------------
extern "C" void kernel_launch(void* const* d_in, const int* in_sizes, int n_in,
                              void* d_out, int out_size) {
    const float* fea     = (const float*)d_in[0];
    const float* score   = (const float*)d_in[1];
    const int*   label   = (const int*)d_in[2];
    const float* t_logit = (const float*)d_in[3];
    const float* ori     = (const float*)d_in[4];
    const float* l2w     = (const float*)d_in[5];
    float* out = (float*)d_out;

    k_reduce<<<B_, 256>>>(score);
    k_select<<<B_, 256>>>(score, label);
    k_gemm<<<dim3(ROWS / BM, ROWS / BN, SPLITK), 256>>>(fea);
    k_rowloss<<<B_, 256>>>();
    k_final<<<1, 32>>>(t_logit, ori, l2w, out);
}

// round 3
// speedup vs baseline: 1.8570x; 1.8570x over previous
#include <cuda_runtime.h>

#define B_    16
#define N_    2048
#define D_    1024
#define KH    15
#define KL    5
#define ROWS  320      // B_*KH + B_*KL
#define HROWS 240      // B_*KH
#define SPLITK 8
#define KC    (D_ / SPLITK)   // 128

// ---------------- scratch (no allocations allowed) ----------------
__device__ unsigned int g_pmax[B_];
__device__ unsigned int g_pmin[B_];
__device__ float        g_psum[B_];
__device__ int          g_idx[ROWS];
__device__ int          g_val[ROWS];
__device__ int          g_lab[ROWS];
__device__ __align__(16) float g_Gk[SPLITK][ROWS * ROWS];
__device__ float        g_per[ROWS];

// ---------------- helpers ----------------
__device__ __forceinline__ unsigned long long u64min(unsigned long long a,
                                                     unsigned long long b) {
    return a < b ? a : b;
}

__device__ __forceinline__ unsigned long long f32x2_fma(unsigned long long c,
                                                        unsigned long long a,
                                                        unsigned long long b) {
    asm("fma.rn.f32x2 %0, %1, %2, %0;" : "+l"(c) : "l"(a), "l"(b));
    return c;
}

__device__ __forceinline__ unsigned long long dup_f32(float x) {
    unsigned long long r;
    unsigned u = __float_as_uint(x);
    asm("mov.b64 %0, {%1, %1};" : "=l"(r) : "r"(u));
    return r;
}

// ---------------- 1: per-bag min/max/sum partials (16 blocks) ----------------
__global__ void k_reduce(const float* __restrict__ score) {
    __shared__ unsigned int smx[8], smn[8];
    __shared__ float ssum[8];
    int b = blockIdx.x, tid = threadIdx.x;
    unsigned int mx = 0u, mn = 0xFFFFFFFFu;
    float s = 0.f;
#pragma unroll
    for (int i = 0; i < 8; i++) {
        float v = score[b * N_ + tid + i * 256];
        unsigned int bb = __float_as_uint(v);   // score >= 0 -> bits monotonic
        mx = max(mx, bb);
        mn = min(mn, bb);
        s += v;
    }
#pragma unroll
    for (int o = 16; o; o >>= 1) {
        mx = max(mx, __shfl_down_sync(0xffffffffu, mx, o));
        mn = min(mn, __shfl_down_sync(0xffffffffu, mn, o));
        s += __shfl_down_sync(0xffffffffu, s, o);
    }
    if ((tid & 31) == 0) { smx[tid >> 5] = mx; smn[tid >> 5] = mn; ssum[tid >> 5] = s; }
    __syncthreads();
    if (tid == 0) {
        for (int w = 1; w < 8; w++) {
            mx = max(mx, smx[w]); mn = min(mn, smn[w]); s += ssum[w];
        }
        g_pmax[b] = mx; g_pmin[b] = mn; g_psum[b] = s;
    }
}

// ---------------- 2: per-bag selection (16 blocks, shuffle extraction) -------
// key = (float_bits(score) << 32) | index  -> lexicographic (score, idx),
// matching jnp stable ascending argsort semantics (score >= 0).
__global__ void k_select(const float* __restrict__ score,
                         const int* __restrict__ label) {
    __shared__ unsigned long long s_w[2][8];
    __shared__ float s_gmax, s_gmin;
    int b = blockIdx.x, tid = threadIdx.x;

    if (tid == 0) {
        unsigned mx = 0u, mn = 0xFFFFFFFFu;
        for (int i = 0; i < B_; i++) { mx = max(mx, g_pmax[i]); mn = min(mn, g_pmin[i]); }
        s_gmax = __uint_as_float(mx);
        s_gmin = __uint_as_float(mn);
    }

    float sc[8];
#pragma unroll
    for (int i = 0; i < 8; i++) sc[i] = score[b * N_ + tid + i * 256];
    __syncthreads();
    float gmax = s_gmax, gmin = s_gmin;

    unsigned long long key[8];
    int parity = 0;

    // ---- HIGH: 15 smallest keys with score in [gmax-0.3, gmax] ----
    {
        float lo = gmax - 0.3f, hi = gmax;
#pragma unroll
        for (int i = 0; i < 8; i++) {
            key[i] = (sc[i] >= lo && sc[i] <= hi)
                ? (((unsigned long long)__float_as_uint(sc[i]) << 32) | (unsigned)(tid + i * 256))
                : ~0ULL;
        }
        for (int t = 0; t < KH; t++) {
            unsigned long long m = key[0];
#pragma unroll
            for (int i = 1; i < 8; i++) m = u64min(m, key[i]);
#pragma unroll
            for (int o = 16; o; o >>= 1) m = u64min(m, __shfl_down_sync(0xffffffffu, m, o));
            if ((tid & 31) == 0) s_w[parity][tid >> 5] = m;
            __syncthreads();
            if (tid < 32) {
                unsigned long long v = (tid < 8) ? s_w[parity][tid] : ~0ULL;
#pragma unroll
                for (int o = 4; o; o >>= 1) v = u64min(v, __shfl_down_sync(0xffffffffu, v, o));
                if (tid == 0) s_w[parity][0] = v;
            }
            __syncthreads();
            unsigned long long best = s_w[parity][0];
            parity ^= 1;
#pragma unroll
            for (int i = 0; i < 8; i++) if (key[i] == best) key[i] = ~0ULL;
            if (tid == 0) {
                int r = b * KH + t;
                if (best != ~0ULL) {
                    g_val[r] = 1;
                    g_idx[r] = b * N_ + (int)(best & 0xFFFFFFFFULL);
                } else {
                    g_val[r] = 0;
                    g_idx[r] = 0;
                }
                g_lab[r] = label[b];
            }
        }
    }

    // ---- LOW: up to 10 smallest keys in [gmin, gmin+1e-9]; keep even ranks --
    {
        float lo = gmin, hi = gmin + 1e-9f;
#pragma unroll
        for (int i = 0; i < 8; i++) {
            key[i] = (sc[i] >= lo && sc[i] <= hi)
                ? (((unsigned long long)__float_as_uint(sc[i]) << 32) | (unsigned)(tid + i * 256))
                : ~0ULL;
        }
        unsigned long long sel[10];
        for (int t = 0; t < 10; t++) {
            unsigned long long m = key[0];
#pragma unroll
            for (int i = 1; i < 8; i++) m = u64min(m, key[i]);
#pragma unroll
            for (int o = 16; o; o >>= 1) m = u64min(m, __shfl_down_sync(0xffffffffu, m, o));
            if ((tid & 31) == 0) s_w[parity][tid >> 5] = m;
            __syncthreads();
            if (tid < 32) {
                unsigned long long v = (tid < 8) ? s_w[parity][tid] : ~0ULL;
#pragma unroll
                for (int o = 4; o; o >>= 1) v = u64min(v, __shfl_down_sync(0xffffffffu, v, o));
                if (tid == 0) s_w[parity][0] = v;
            }
            __syncthreads();
            unsigned long long best = s_w[parity][0];
            parity ^= 1;
#pragma unroll
            for (int i = 0; i < 8; i++) if (key[i] == best) key[i] = ~0ULL;
            sel[t] = best;
        }
        if (tid == 0) {
            for (int j = 0; j < KL; j++) {
                unsigned long long k = sel[2 * j];
                int r = HROWS + b * KL + j;
                if (k != ~0ULL) {
                    g_val[r] = 1;
                    g_idx[r] = b * N_ + (int)(k & 0xFFFFFFFFULL);
                } else {
                    g_val[r] = 0;
                    g_idx[r] = 0;
                }
                g_lab[r] = 2;  // N_CLASSES
            }
        }
    }
}

// ---- 3: gram G = X X^T (320x320, K=1024) with fused gather, f32x2 FMA ------
#define BM 64
#define BN 64
#define BK 16
__global__ void __launch_bounds__(256) k_gemm(const float* __restrict__ fea) {
    __shared__ __align__(16) float As[BK][BM + 2];
    __shared__ __align__(16) float Bs[BK][BN + 2];
    int bm = blockIdx.x, bn = blockIdx.y, kz = blockIdx.z;
    int tid = threadIdx.x;
    int tx = tid & 15, ty = tid >> 4;
    int tx4 = tx * 4, ty4 = ty * 4;

    unsigned long long cc[4][2];
#pragma unroll
    for (int i = 0; i < 4; i++) { cc[i][0] = 0ULL; cc[i][1] = 0ULL; }

    int loadRow = tid >> 2;           // 0..63
    int loadK4  = (tid & 3) * 4;      // 0,4,8,12
    // indirect gather: invalid rows point at row 0; masked in k_rowloss
    const float* A0 = fea + (size_t)g_idx[bm * BM + loadRow] * D_ + kz * KC;
    const float* B0 = fea + (size_t)g_idx[bn * BN + loadRow] * D_ + kz * KC;

    for (int k0 = 0; k0 < KC; k0 += BK) {
        float4 a  = *(const float4*)(A0 + k0 + loadK4);
        float4 b4 = *(const float4*)(B0 + k0 + loadK4);
        As[loadK4 + 0][loadRow] = a.x;
        As[loadK4 + 1][loadRow] = a.y;
        As[loadK4 + 2][loadRow] = a.z;
        As[loadK4 + 3][loadRow] = a.w;
        Bs[loadK4 + 0][loadRow] = b4.x;
        Bs[loadK4 + 1][loadRow] = b4.y;
        Bs[loadK4 + 2][loadRow] = b4.z;
        Bs[loadK4 + 3][loadRow] = b4.w;
        __syncthreads();
#pragma unroll
        for (int k = 0; k < BK; k++) {
            float2 a01 = *(const float2*)&As[k][ty4];
            float2 a23 = *(const float2*)&As[k][ty4 + 2];
            unsigned long long bp0 = *(const unsigned long long*)&Bs[k][tx4];
            unsigned long long bp1 = *(const unsigned long long*)&Bs[k][tx4 + 2];
            unsigned long long A0d = dup_f32(a01.x);
            unsigned long long A1d = dup_f32(a01.y);
            unsigned long long A2d = dup_f32(a23.x);
            unsigned long long A3d = dup_f32(a23.y);
            cc[0][0] = f32x2_fma(cc[0][0], A0d, bp0);
            cc[0][1] = f32x2_fma(cc[0][1], A0d, bp1);
            cc[1][0] = f32x2_fma(cc[1][0], A1d, bp0);
            cc[1][1] = f32x2_fma(cc[1][1], A1d, bp1);
            cc[2][0] = f32x2_fma(cc[2][0], A2d, bp0);
            cc[2][1] = f32x2_fma(cc[2][1], A2d, bp1);
            cc[3][0] = f32x2_fma(cc[3][0], A3d, bp0);
            cc[3][1] = f32x2_fma(cc[3][1], A3d, bp1);
        }
        __syncthreads();
    }

    float* out = g_Gk[kz];
#pragma unroll
    for (int i = 0; i < 4; i++) {
        unsigned lo0, hi0, lo1, hi1;
        asm("mov.b64 {%0, %1}, %2;" : "=r"(lo0), "=r"(hi0) : "l"(cc[i][0]));
        asm("mov.b64 {%0, %1}, %2;" : "=r"(lo1), "=r"(hi1) : "l"(cc[i][1]));
        float4 v = make_float4(__uint_as_float(lo0), __uint_as_float(hi0),
                               __uint_as_float(lo1), __uint_as_float(hi1));
        int row = bm * BM + ty4 + i;
        *(float4*)(out + (size_t)row * ROWS + bn * BN + tx4) = v;
    }
}

// ---------------- 4: per-query loss (320 blocks x 128 threads) ----------------
__global__ void __launch_bounds__(128) k_rowloss() {
    __shared__ float s_den[4], s_num[4];
    int q = blockIdx.x, tid = threadIdx.x;
    int labq = g_lab[q];
    float den = 0.f, num = 0.f;
    for (int n = tid; n < ROWS; n += 128) {
        float g = 0.f;
#pragma unroll
        for (int s = 0; s < SPLITK; s++) g += g_Gk[s][q * ROWS + n];
        float e = expf(g * 0.0625f);     // TAU = 16
        e = g_val[n] ? e : 0.f;
        den += e;
        if (g_lab[n] == labq) num += e;
    }
#pragma unroll
    for (int o = 16; o; o >>= 1) {
        den += __shfl_down_sync(0xffffffffu, den, o);
        num += __shfl_down_sync(0xffffffffu, num, o);
    }
    if ((tid & 31) == 0) { s_den[tid >> 5] = den; s_num[tid >> 5] = num; }
    __syncthreads();
    if (tid == 0) {
        float d = s_den[0] + s_den[1] + s_den[2] + s_den[3];
        float nm = s_num[0] + s_num[1] + s_num[2] + s_num[3];
        g_per[q] = g_val[q] ? -logf(nm / d) : 0.f;
    }
}

// ---------------- 5: final scalar ----------------
__global__ void k_final(const float* __restrict__ t_logit,
                        const float* __restrict__ ori,
                        const float* __restrict__ l2w,
                        float* __restrict__ out) {
    __shared__ float s_c[16];
    int tid = threadIdx.x;
    if (tid < 16) {
        float s = 0.f; int c = 0;
        for (int k = 0; k < KH; k++) { int r = tid * KH + k; s += g_per[r]; c += g_val[r]; }
        for (int k = 0; k < KL; k++) { int r = HROWS + tid * KL + k; s += g_per[r]; c += g_val[r]; }
        s_c[tid] = s / (float)c;
    }
    __syncthreads();
    if (tid == 0) {
        float contr = 0.f;
        for (int b = 0; b < B_; b++) contr += s_c[b];
        contr /= (float)B_;

        float t = t_logit[0];
        float ce = 0.f;
        for (int b = 0; b < B_; b++) {
            float se = expf(ori[b * 2 + 0]) + expf(ori[b * 2 + 1]);
            ce += -logf(expf(t) / se);
        }
        ce /= (float)B_;

        unsigned mx = 0u;
        float sum = 0.f;
        for (int i = 0; i < B_; i++) { mx = max(mx, g_pmax[i]); sum += g_psum[i]; }
        float gmax = __uint_as_float(mx);
        float meanv = sum / (float)(B_ * N_);
        float Dm = meanv / gmax;
        float l2 = 0.0001f * (1.f - Dm) * (1.f - Dm) * l2w[0];

        out[0] = contr + ce + l2;
    }
}

// ---------------- launch ----------------
extern "C" void kernel_launch(void* const* d_in, const int* in_sizes, int n_in,
                              void* d_out, int out_size) {
    const float* fea     = (const float*)d_in[0];
    const float* score   = (const float*)d_in[1];
    const int*   label   = (const int*)d_in[2];
    const float* t_logit = (const float*)d_in[3];
    const float* ori     = (const float*)d_in[4];
    const float* l2w     = (const float*)d_in[5];
    float* out = (float*)d_out;

    k_reduce<<<B_, 256>>>(score);
    k_select<<<B_, 256>>>(score, label);
    k_gemm<<<dim3(ROWS / BM, ROWS / BN, SPLITK), 256>>>(fea);
    k_rowloss<<<ROWS, 128>>>();
    k_final<<<1, 32>>>(t_logit, ori, l2w, out);
}